// round 2
// baseline (speedup 1.0000x reference)
#include <cuda_runtime.h>
#include <math.h>

// Problem constants (fixed by setup_inputs)
#define NN      65536     // total nodes
#define BB      512       // graphs
#define NPG     128       // nodes per graph
#define EE      262144    // edges
#define EPG     512       // edges per graph (contiguous, intra-graph)
#define HH      256       // hidden
#define FIN     128       // input features
#define BN_EPS  1e-5f

typedef unsigned long long u64;

// ---------------- f32x2 packed-FMA helpers (sm_103a FFMA2) -----------------
__device__ __forceinline__ u64 pack2(float lo, float hi) {
    u64 r;
    asm("mov.b64 %0, {%1, %2};" : "=l"(r) : "f"(lo), "f"(hi));
    return r;
}
__device__ __forceinline__ void unpack2(u64 v, float& lo, float& hi) {
    asm("mov.b64 {%0, %1}, %2;" : "=f"(lo), "=f"(hi) : "l"(v));
}
__device__ __forceinline__ u64 fma2(u64 a, u64 b, u64 c) {
    u64 d;
    asm("fma.rn.f32x2 %0, %1, %2, %3;" : "=l"(d) : "l"(a), "l"(b), "l"(c));
    return d;
}

// ---------------- scratch (device globals; no cudaMalloc allowed) ----------
__device__ float d_z[NN * HH];   // 64 MB
__device__ float d_t[NN * HH];   // 64 MB
__device__ float d_h[NN * HH];   // 64 MB
__device__ float d_a[NN * 2];
__device__ float d_stats[2 * HH];
__device__ float d_pen[BB];

// ---------------- per-graph aggregation: z = h + sum_{(s,d) in E_g} h[s] ---
template <int F>
__global__ void agg_kernel(const float* __restrict__ hin,
                           const int* __restrict__ src,
                           const int* __restrict__ dst,
                           float* __restrict__ zout) {
    extern __shared__ float sagg[];             // NPG * F floats
    const int g = blockIdx.x;
    const int t = threadIdx.x;                  // 0..F-1
    for (int i = t; i < NPG * F; i += F) sagg[i] = 0.f;
    __syncthreads();
    const int ebase = g * EPG;
    const int nbase = g * NPG;
    #pragma unroll 4
    for (int e = 0; e < EPG; ++e) {
        int s  = src[ebase + e];
        int dl = dst[ebase + e] - nbase;
        sagg[dl * F + t] += hin[(size_t)s * F + t];
    }
    __syncthreads();
    const size_t gb = (size_t)g * NPG * F;
    for (int i = t; i < NPG * F; i += F)
        zout[gb + i] = sagg[i] + hin[gb + i];
}

// ---------------- SGEMM (FFMA2): C = act(A[M,K] @ W[K,N] + bias) -----------
// 128x128 tile, BK=8, 8x8 per thread (4 f32x2 pairs wide), 256 threads.
#define BM 128
#define BN 128
#define BK 8
#define TM 8
#define TN 8

__global__ __launch_bounds__(256)
void sgemm_bias_act(const float* __restrict__ A, const float* __restrict__ W,
                    const float* __restrict__ bias, float* __restrict__ C,
                    int M, int K, int Ncol, int act) {
    __shared__ __align__(16) float As[BK][BM];
    __shared__ __align__(16) float Bs[BK][BN];
    const int tid = threadIdx.x;
    const int rowBase = blockIdx.y * BM;
    const int colBase = blockIdx.x * BN;
    const int aRow = tid >> 1;            // 0..127
    const int aCol = (tid & 1) * 4;       // 0 or 4
    const int bRow = tid >> 5;            // 0..7
    const int bCol = (tid & 31) * 4;      // 0..124
    const int tRow = (tid >> 4) * TM;
    const int tCol = (tid & 15) * TN;

    u64 acc[TM][TN / 2] = {};             // packed f32x2 accumulators

    for (int k0 = 0; k0 < K; k0 += BK) {
        float4 av = *reinterpret_cast<const float4*>(
            &A[(size_t)(rowBase + aRow) * K + k0 + aCol]);
        As[aCol + 0][aRow] = av.x;
        As[aCol + 1][aRow] = av.y;
        As[aCol + 2][aRow] = av.z;
        As[aCol + 3][aRow] = av.w;
        *reinterpret_cast<float4*>(&Bs[bRow][bCol]) =
            *reinterpret_cast<const float4*>(
                &W[(size_t)(k0 + bRow) * Ncol + colBase + bCol]);
        __syncthreads();
        #pragma unroll
        for (int kk = 0; kk < BK; ++kk) {
            float4 m0 = *reinterpret_cast<const float4*>(&As[kk][tRow]);
            float4 m1 = *reinterpret_cast<const float4*>(&As[kk][tRow + 4]);
            ulonglong2 n0 = *reinterpret_cast<const ulonglong2*>(&Bs[kk][tCol]);
            ulonglong2 n1 = *reinterpret_cast<const ulonglong2*>(&Bs[kk][tCol + 4]);
            u64 rn[4] = {n0.x, n0.y, n1.x, n1.y};
            float rm[8] = {m0.x, m0.y, m0.z, m0.w, m1.x, m1.y, m1.z, m1.w};
            #pragma unroll
            for (int i = 0; i < TM; ++i) {
                u64 mm = pack2(rm[i], rm[i]);
                #pragma unroll
                for (int j = 0; j < TN / 2; ++j)
                    acc[i][j] = fma2(mm, rn[j], acc[i][j]);
            }
        }
        __syncthreads();
    }
    #pragma unroll
    for (int i = 0; i < TM; ++i) {
        const int row = rowBase + tRow + i;
        float vals[TN];
        #pragma unroll
        for (int j = 0; j < TN / 2; ++j)
            unpack2(acc[i][j], vals[2 * j], vals[2 * j + 1]);
        #pragma unroll
        for (int j = 0; j < TN; ++j) {
            const int col = colBase + tCol + j;
            float c = vals[j] + bias[col];
            if (act == 1) c = fmaxf(c, 0.f);
            else if (act == 2) c = tanhf(c);
            vals[j] = c;
        }
        #pragma unroll
        for (int j = 0; j < TN; j += 4)
            *reinterpret_cast<float4*>(&C[(size_t)row * Ncol + colBase + tCol + j]) =
                make_float4(vals[j], vals[j + 1], vals[j + 2], vals[j + 3]);
    }
}

// ---------------- BatchNorm (training-mode batch stats) --------------------
__global__ void bn_zero_kernel() {
    if (threadIdx.x < 2 * HH) d_stats[threadIdx.x] = 0.f;
}

__global__ void bn_stats_kernel(const float* __restrict__ Z) {
    const int t = threadIdx.x;              // feature 0..255
    const int r0 = blockIdx.x * 256;        // 256 rows per block
    float s = 0.f, s2 = 0.f;
    for (int r = 0; r < 256; ++r) {
        float v = Z[(size_t)(r0 + r) * HH + t];
        s += v; s2 += v * v;
    }
    atomicAdd(&d_stats[t], s);
    atomicAdd(&d_stats[HH + t], s2);
}

__global__ void bn_apply_kernel(const float* __restrict__ Z,
                                const float* __restrict__ gamma,
                                const float* __restrict__ beta,
                                float* __restrict__ Hout) {
    const int idx = blockIdx.x * blockDim.x + threadIdx.x;
    const int f = idx & (HH - 1);
    const float mu  = d_stats[f] * (1.f / NN);
    const float var = d_stats[HH + f] * (1.f / NN) - mu * mu;
    const float inv = rsqrtf(var + BN_EPS);
    Hout[idx] = (Z[idx] - mu) * inv * gamma[f] + beta[f];
}

// ---------------- assignment softmax: a = softmax(T @ c2w + c2b) -----------
__global__ void assign_kernel(const float* __restrict__ T,
                              const float* __restrict__ c2w,
                              const float* __restrict__ c2b,
                              float* __restrict__ Aout) {
    const int lane = threadIdx.x & 31;
    const int row = blockIdx.x * 8 + (threadIdx.x >> 5);
    float s0 = 0.f, s1 = 0.f;
    #pragma unroll
    for (int k = lane; k < HH; k += 32) {
        float tv = T[(size_t)row * HH + k];
        s0 += tv * c2w[k * 2 + 0];
        s1 += tv * c2w[k * 2 + 1];
    }
    #pragma unroll
    for (int o = 16; o > 0; o >>= 1) {
        s0 += __shfl_xor_sync(0xffffffffu, s0, o);
        s1 += __shfl_xor_sync(0xffffffffu, s1, o);
    }
    if (lane == 0) {
        s0 += c2b[0]; s1 += c2b[1];
        float m = fmaxf(s0, s1);
        float e0 = expf(s0 - m), e1 = expf(s1 - m);
        float inv = 1.f / (e0 + e1);
        Aout[row * 2 + 0] = e0 * inv;
        Aout[row * 2 + 1] = e1 * inv;
    }
}

// ---------------- pooling: sub & graph embeddings (block per graph) --------
__global__ void pool_kernel(const float* __restrict__ Hh,
                            const float* __restrict__ Aa,
                            float* __restrict__ sub_out,
                            float* __restrict__ graph_out) {
    __shared__ float sa0[NPG];
    const int g = blockIdx.x, t = threadIdx.x;   // 256 threads
    if (t < NPG) sa0[t] = Aa[(g * NPG + t) * 2];
    __syncthreads();
    float sh = 0.f, ss = 0.f;
    const size_t base = (size_t)g * NPG * HH;
    for (int r = 0; r < NPG; ++r) {
        float hv = Hh[base + r * HH + t];
        sh += hv;
        ss += sa0[r] * hv;
    }
    sub_out[g * HH + t] = ss;
    graph_out[g * HH + t] = sh * (1.f / NPG);
}

// ---------------- pooled adjacency diag penalty (block per graph) ----------
__global__ void adj_kernel(const float* __restrict__ Aa,
                           const int* __restrict__ src,
                           const int* __restrict__ dst) {
    const int g = blockIdx.x, t = threadIdx.x;   // 128 threads
    float m00 = 0.f, m01 = 0.f, m10 = 0.f, m11 = 0.f;
    for (int e = t; e < EPG; e += 128) {
        int se = src[g * EPG + e], de = dst[g * EPG + e];
        float a0 = Aa[se * 2], a1 = Aa[se * 2 + 1];
        float b0 = Aa[de * 2], b1 = Aa[de * 2 + 1];
        m00 += a0 * b0; m01 += a0 * b1;
        m10 += a1 * b0; m11 += a1 * b1;
    }
    __shared__ float red[4][128];
    red[0][t] = m00; red[1][t] = m01; red[2][t] = m10; red[3][t] = m11;
    __syncthreads();
    for (int s = 64; s > 0; s >>= 1) {
        if (t < s) {
            red[0][t] += red[0][t + s]; red[1][t] += red[1][t + s];
            red[2][t] += red[2][t + s]; red[3][t] += red[3][t + s];
        }
        __syncthreads();
    }
    if (t == 0) {
        float r0 = fmaxf(fabsf(red[0][0]) + fabsf(red[1][0]), 1e-12f);
        float r1 = fmaxf(fabsf(red[2][0]) + fabsf(red[3][0]), 1e-12f);
        float e0 = red[0][0] / r0 - 1.f;
        float e1 = red[3][0] / r1 - 1.f;
        d_pen[g] = 0.5f * (e0 * e0 + e1 * e1);
    }
}

__global__ void pen_reduce_kernel(float* __restrict__ outp) {
    __shared__ float s[BB];
    s[threadIdx.x] = d_pen[threadIdx.x];
    __syncthreads();
    for (int st = BB / 2; st > 0; st >>= 1) {
        if (threadIdx.x < st) s[threadIdx.x] += s[threadIdx.x + st];
        __syncthreads();
    }
    if (threadIdx.x == 0) outp[0] = s[0] * (1.f / BB);
}

// ---------------- classifier head (block per graph) ------------------------
__global__ void head_kernel(const float* __restrict__ sub,
                            const float* __restrict__ l1w,
                            const float* __restrict__ l1b,
                            const float* __restrict__ l2w,
                            const float* __restrict__ l2b,
                            float* __restrict__ outp) {
    __shared__ float ssub[HH];
    __shared__ float red0[HH], red1[HH];
    const int r = blockIdx.x, t = threadIdx.x;   // 256 threads
    ssub[t] = sub[r * HH + t];
    __syncthreads();
    float acc = l1b[t];
    #pragma unroll 8
    for (int k = 0; k < HH; ++k) acc += ssub[k] * l1w[k * HH + t];
    float zc = fmaxf(acc, 0.f);
    red0[t] = zc * l2w[t * 2 + 0];
    red1[t] = zc * l2w[t * 2 + 1];
    __syncthreads();
    for (int s = 128; s > 0; s >>= 1) {
        if (t < s) { red0[t] += red0[t + s]; red1[t] += red1[t + s]; }
        __syncthreads();
    }
    if (t == 0) {
        float s0 = red0[0] + l2b[0], s1 = red1[0] + l2b[1];
        float m = fmaxf(s0, s1);
        float lse = m + logf(expf(s0 - m) + expf(s1 - m));
        outp[r * 2 + 0] = s0 - lse;
        outp[r * 2 + 1] = s1 - lse;
    }
}

// ---------------- launch ----------------------------------------------------
extern "C" void kernel_launch(void* const* d_in, const int* in_sizes, int n_in,
                              void* d_out, int out_size) {
    const float* x    = (const float*)d_in[0];
    const int*   ei   = (const int*)d_in[1];
    const int*   src  = ei;
    const int*   dst  = ei + EE;
    const float* w0_1 = (const float*)d_in[3];
    const float* b0_1 = (const float*)d_in[4];
    const float* w0_2 = (const float*)d_in[5];
    const float* b0_2 = (const float*)d_in[6];
    const float* g0   = (const float*)d_in[7];
    const float* be0  = (const float*)d_in[8];
    const float* wl1  = (const float*)d_in[9];
    const float* bl1  = (const float*)d_in[10];
    const float* wl2  = (const float*)d_in[11];
    const float* bl2  = (const float*)d_in[12];
    const float* gl   = (const float*)d_in[13];
    const float* bel  = (const float*)d_in[14];
    const float* c1w  = (const float*)d_in[15];
    const float* c1b  = (const float*)d_in[16];
    const float* c2w  = (const float*)d_in[17];
    const float* c2b  = (const float*)d_in[18];
    const float* l1w  = (const float*)d_in[19];
    const float* l1b  = (const float*)d_in[20];
    const float* l2w  = (const float*)d_in[21];
    const float* l2b  = (const float*)d_in[22];

    float* out        = (float*)d_out;
    float* out_logits = out;                         // [B, 2]
    float* out_sub    = out + BB * 2;                // [B, H]
    float* out_graph  = out + BB * 2 + BB * HH;      // [B, H]
    float* out_pen    = out + BB * 2 + 2 * BB * HH;  // scalar

    float *zb, *tb, *hb, *ab;
    cudaGetSymbolAddress((void**)&zb, d_z);
    cudaGetSymbolAddress((void**)&tb, d_t);
    cudaGetSymbolAddress((void**)&hb, d_h);
    cudaGetSymbolAddress((void**)&ab, d_a);

    cudaFuncSetAttribute(agg_kernel<FIN>, cudaFuncAttributeMaxDynamicSharedMemorySize,
                         NPG * FIN * 4);
    cudaFuncSetAttribute(agg_kernel<HH>, cudaFuncAttributeMaxDynamicSharedMemorySize,
                         NPG * HH * 4);

    const dim3 gemm_grid(HH / BN, NN / BM);

    // ---- GIN layer 0 (F_IN -> H -> H) ----
    agg_kernel<FIN><<<BB, FIN, NPG * FIN * 4>>>(x, src, dst, zb);
    sgemm_bias_act<<<gemm_grid, 256>>>(zb, w0_1, b0_1, tb, NN, FIN, HH, 1);
    sgemm_bias_act<<<gemm_grid, 256>>>(tb, w0_2, b0_2, zb, NN, HH, HH, 1);
    bn_zero_kernel<<<1, 512>>>();
    bn_stats_kernel<<<NN / 256, 256>>>(zb);
    bn_apply_kernel<<<(NN * HH) / 256, 256>>>(zb, g0, be0, hb);

    // ---- GIN layers 1..2 (H -> H -> H) ----
    for (int i = 0; i < 2; ++i) {
        agg_kernel<HH><<<BB, HH, NPG * HH * 4>>>(hb, src, dst, zb);
        sgemm_bias_act<<<gemm_grid, 256>>>(zb, wl1 + i * HH * HH, bl1 + i * HH,
                                           tb, NN, HH, HH, 1);
        sgemm_bias_act<<<gemm_grid, 256>>>(tb, wl2 + i * HH * HH, bl2 + i * HH,
                                           zb, NN, HH, HH, 1);
        bn_zero_kernel<<<1, 512>>>();
        bn_stats_kernel<<<NN / 256, 256>>>(zb);
        bn_apply_kernel<<<(NN * HH) / 256, 256>>>(zb, gl + i * HH, bel + i * HH, hb);
    }

    // ---- assignment: a = softmax(tanh(h@c1w+c1b) @ c2w + c2b) ----
    sgemm_bias_act<<<gemm_grid, 256>>>(hb, c1w, c1b, tb, NN, HH, HH, 2);
    assign_kernel<<<NN / 8, 256>>>(tb, c2w, c2b, ab);

    // ---- pooling / penalty / head ----
    pool_kernel<<<BB, 256>>>(hb, ab, out_sub, out_graph);
    adj_kernel<<<BB, 128>>>(ab, src, dst);
    pen_reduce_kernel<<<1, BB>>>(out_pen);
    head_kernel<<<BB, 256>>>(out_sub, l1w, l1b, l2w, l2b, out_logits);
}

// round 3
// speedup vs baseline: 1.5872x; 1.5872x over previous
#include <cuda_runtime.h>
#include <cuda_bf16.h>
#include <math.h>

// Problem constants (fixed by setup_inputs)
#define NN      65536     // total nodes
#define BB      512       // graphs
#define NPG     128       // nodes per graph
#define EE      262144    // edges
#define EPG     512       // edges per graph (contiguous, intra-graph)
#define HH      256       // hidden
#define FIN     128       // input features
#define BN_EPS  1e-5f

// ---------------- scratch (device globals; no cudaMalloc allowed) ----------
__device__ float d_z[NN * HH];   // 64 MB
__device__ float d_t[NN * HH];   // 64 MB
__device__ float d_h[NN * HH];   // 64 MB
__device__ float d_a[NN * 2];
__device__ float d_stats[2 * HH];
__device__ float d_pen[BB];

// ---------------- MMA helpers ----------------------------------------------
__device__ __forceinline__ unsigned smem_u32(const void* p) {
    return (unsigned)__cvta_generic_to_shared(p);
}
__device__ __forceinline__ void ldsm_x4(unsigned addr, unsigned& r0, unsigned& r1,
                                        unsigned& r2, unsigned& r3) {
    asm volatile("ldmatrix.sync.aligned.m8n8.x4.shared.b16 {%0,%1,%2,%3}, [%4];"
                 : "=r"(r0), "=r"(r1), "=r"(r2), "=r"(r3) : "r"(addr));
}
__device__ __forceinline__ void ldsm_x4t(unsigned addr, unsigned& r0, unsigned& r1,
                                         unsigned& r2, unsigned& r3) {
    asm volatile("ldmatrix.sync.aligned.m8n8.x4.trans.shared.b16 {%0,%1,%2,%3}, [%4];"
                 : "=r"(r0), "=r"(r1), "=r"(r2), "=r"(r3) : "r"(addr));
}
__device__ __forceinline__ void mma_bf16(float* d, const unsigned* a,
                                         unsigned b0, unsigned b1) {
    asm volatile("mma.sync.aligned.m16n8k16.row.col.f32.bf16.bf16.f32 "
                 "{%0,%1,%2,%3}, {%4,%5,%6,%7}, {%8,%9}, {%0,%1,%2,%3};"
                 : "+f"(d[0]), "+f"(d[1]), "+f"(d[2]), "+f"(d[3])
                 : "r"(a[0]), "r"(a[1]), "r"(a[2]), "r"(a[3]), "r"(b0), "r"(b1));
}

// ---------------- per-graph aggregation: z = h + sum_{(s,d) in E_g} h[s] ---
template <int F>
__global__ void agg_kernel(const float* __restrict__ hin,
                           const int* __restrict__ src,
                           const int* __restrict__ dst,
                           float* __restrict__ zout) {
    extern __shared__ float sagg[];             // NPG * F floats
    const int g = blockIdx.x;
    const int t = threadIdx.x;                  // 0..F-1
    for (int i = t; i < NPG * F; i += F) sagg[i] = 0.f;
    __syncthreads();
    const int ebase = g * EPG;
    const int nbase = g * NPG;
    #pragma unroll 4
    for (int e = 0; e < EPG; ++e) {
        int s  = src[ebase + e];
        int dl = dst[ebase + e] - nbase;
        sagg[dl * F + t] += hin[(size_t)s * F + t];
    }
    __syncthreads();
    const size_t gb = (size_t)g * NPG * F;
    for (int i = t; i < NPG * F; i += F)
        zout[gb + i] = sagg[i] + hin[gb + i];
}

// ---------------- bf16x3 tensor-core GEMM: C = act(A@W + bias) -------------
// Block tile 128x128, BK=32, 256 threads (8 warps as 4x2), warp tile 32x64.
// A split into bf16 hi/lo in smem (padded LDA=40), W likewise (LDW=136).
// Three passes: Ah*Wh + Al*Wh + Ah*Wl accumulated in fp32 (err ~2^-16).
#define LDA 40
#define LDW 136

__global__ __launch_bounds__(256)
void gemm_bf16x3(const float* __restrict__ A, const float* __restrict__ W,
                 const float* __restrict__ bias, float* __restrict__ C,
                 int K, int Ncol, int act) {
    __shared__ __align__(16) __nv_bfloat16 As[2][128][LDA];
    __shared__ __align__(16) __nv_bfloat16 Ws[2][32][LDW];

    const int tid = threadIdx.x;
    const int lane = tid & 31;
    const int wid = tid >> 5;
    const int warp_m = wid & 3;        // 0..3  (rows, 32 each)
    const int warp_n = wid >> 2;       // 0..1  (cols, 64 each)
    const int rowBase = blockIdx.y * 128;
    const int colBase = blockIdx.x * 128;

    float acc[2][8][4] = {};           // [mt][nt][frag]

    // ldmatrix lane addressing (precomputed element indices)
    const int lg = lane >> 3, lj = lane & 7;
    // A: row = mbase + (lg&1)*8 + lj ; col = kbase + (lg>>1)*8
    const int a_row_off = (lg & 1) * 8 + lj;
    const int a_col_off = (lg >> 1) * 8;
    // B: k = kbase + (lg&1)*8 + lj ; n = nbase + (lg>>1)*8
    const int b_k_off = (lg & 1) * 8 + lj;
    const int b_n_off = (lg >> 1) * 8;

    for (int k0 = 0; k0 < K; k0 += 32) {
        __syncthreads();
        // ---- load + split A tile (128x32) ----
        #pragma unroll
        for (int i = 0; i < 4; ++i) {
            int idx = tid + i * 256;
            int row = idx >> 3;
            int c = (idx & 7) * 4;
            float4 v = *reinterpret_cast<const float4*>(
                &A[(size_t)(rowBase + row) * K + k0 + c]);
            float vv[4] = {v.x, v.y, v.z, v.w};
            #pragma unroll
            for (int q = 0; q < 4; ++q) {
                __nv_bfloat16 h = __float2bfloat16(vv[q]);
                __nv_bfloat16 l = __float2bfloat16(vv[q] - __bfloat162float(h));
                As[0][row][c + q] = h;
                As[1][row][c + q] = l;
            }
        }
        // ---- load + split W tile (32x128) ----
        #pragma unroll
        for (int i = 0; i < 4; ++i) {
            int idx = tid + i * 256;
            int row = idx >> 5;
            int c = (idx & 31) * 4;
            float4 v = *reinterpret_cast<const float4*>(
                &W[(size_t)(k0 + row) * Ncol + colBase + c]);
            float vv[4] = {v.x, v.y, v.z, v.w};
            #pragma unroll
            for (int q = 0; q < 4; ++q) {
                __nv_bfloat16 h = __float2bfloat16(vv[q]);
                __nv_bfloat16 l = __float2bfloat16(vv[q] - __bfloat162float(h));
                Ws[0][row][c + q] = h;
                Ws[1][row][c + q] = l;
            }
        }
        __syncthreads();

        #pragma unroll
        for (int ks = 0; ks < 2; ++ks) {          // two k16 steps
            const int kb = ks * 16;
            unsigned afr[2][2][4];                 // [split][mt][4]
            #pragma unroll
            for (int s = 0; s < 2; ++s)
                #pragma unroll
                for (int mt = 0; mt < 2; ++mt) {
                    int row = warp_m * 32 + mt * 16 + a_row_off;
                    int col = kb + a_col_off;
                    ldsm_x4(smem_u32(&As[s][row][col]),
                            afr[s][mt][0], afr[s][mt][1], afr[s][mt][2], afr[s][mt][3]);
                }
            unsigned bfr[4][4];                    // [n16 pair][4]
            // W split 0 (hi): passes Ah*Wh and Al*Wh
            #pragma unroll
            for (int p = 0; p < 4; ++p) {
                int kk = kb + b_k_off;
                int nn = warp_n * 64 + p * 16 + b_n_off;
                ldsm_x4t(smem_u32(&Ws[0][kk][nn]),
                         bfr[p][0], bfr[p][1], bfr[p][2], bfr[p][3]);
            }
            #pragma unroll
            for (int s = 0; s < 2; ++s)
                #pragma unroll
                for (int mt = 0; mt < 2; ++mt)
                    #pragma unroll
                    for (int p = 0; p < 4; ++p) {
                        mma_bf16(acc[mt][2 * p],     afr[s][mt], bfr[p][0], bfr[p][1]);
                        mma_bf16(acc[mt][2 * p + 1], afr[s][mt], bfr[p][2], bfr[p][3]);
                    }
            // W split 1 (lo): pass Ah*Wl
            #pragma unroll
            for (int p = 0; p < 4; ++p) {
                int kk = kb + b_k_off;
                int nn = warp_n * 64 + p * 16 + b_n_off;
                ldsm_x4t(smem_u32(&Ws[1][kk][nn]),
                         bfr[p][0], bfr[p][1], bfr[p][2], bfr[p][3]);
            }
            #pragma unroll
            for (int mt = 0; mt < 2; ++mt)
                #pragma unroll
                for (int p = 0; p < 4; ++p) {
                    mma_bf16(acc[mt][2 * p],     afr[0][mt], bfr[p][0], bfr[p][1]);
                    mma_bf16(acc[mt][2 * p + 1], afr[0][mt], bfr[p][2], bfr[p][3]);
                }
        }
    }

    // ---- epilogue: bias + activation + store ----
    const int g = lane >> 2, tq = lane & 3;
    #pragma unroll
    for (int mt = 0; mt < 2; ++mt) {
        #pragma unroll
        for (int nt = 0; nt < 8; ++nt) {
            int row0 = rowBase + warp_m * 32 + mt * 16 + g;
            int col = colBase + warp_n * 64 + nt * 8 + 2 * tq;
            float b0 = bias[col], b1 = bias[col + 1];
            float v[4] = {acc[mt][nt][0] + b0, acc[mt][nt][1] + b1,
                          acc[mt][nt][2] + b0, acc[mt][nt][3] + b1};
            if (act == 1) {
                #pragma unroll
                for (int q = 0; q < 4; ++q) v[q] = fmaxf(v[q], 0.f);
            } else if (act == 2) {
                #pragma unroll
                for (int q = 0; q < 4; ++q) v[q] = tanhf(v[q]);
            }
            *reinterpret_cast<float2*>(&C[(size_t)row0 * Ncol + col]) =
                make_float2(v[0], v[1]);
            *reinterpret_cast<float2*>(&C[(size_t)(row0 + 8) * Ncol + col]) =
                make_float2(v[2], v[3]);
        }
    }
}

// ---------------- BatchNorm (training-mode batch stats) --------------------
__global__ void bn_zero_kernel() {
    if (threadIdx.x < 2 * HH) d_stats[threadIdx.x] = 0.f;
}

__global__ void bn_stats_kernel(const float* __restrict__ Z) {
    const int t = threadIdx.x;              // feature 0..255
    const int r0 = blockIdx.x * 256;        // 256 rows per block
    float s = 0.f, s2 = 0.f;
    for (int r = 0; r < 256; ++r) {
        float v = Z[(size_t)(r0 + r) * HH + t];
        s += v; s2 += v * v;
    }
    atomicAdd(&d_stats[t], s);
    atomicAdd(&d_stats[HH + t], s2);
}

__global__ void bn_apply_kernel(const float* __restrict__ Z,
                                const float* __restrict__ gamma,
                                const float* __restrict__ beta,
                                float* __restrict__ Hout) {
    const int idx = blockIdx.x * blockDim.x + threadIdx.x;
    const int f = idx & (HH - 1);
    const float mu  = d_stats[f] * (1.f / NN);
    const float var = d_stats[HH + f] * (1.f / NN) - mu * mu;
    const float inv = rsqrtf(var + BN_EPS);
    Hout[idx] = (Z[idx] - mu) * inv * gamma[f] + beta[f];
}

// ---------------- assignment softmax: a = softmax(T @ c2w + c2b) -----------
__global__ void assign_kernel(const float* __restrict__ T,
                              const float* __restrict__ c2w,
                              const float* __restrict__ c2b,
                              float* __restrict__ Aout) {
    const int lane = threadIdx.x & 31;
    const int row = blockIdx.x * 8 + (threadIdx.x >> 5);
    float s0 = 0.f, s1 = 0.f;
    #pragma unroll
    for (int k = lane; k < HH; k += 32) {
        float tv = T[(size_t)row * HH + k];
        s0 += tv * c2w[k * 2 + 0];
        s1 += tv * c2w[k * 2 + 1];
    }
    #pragma unroll
    for (int o = 16; o > 0; o >>= 1) {
        s0 += __shfl_xor_sync(0xffffffffu, s0, o);
        s1 += __shfl_xor_sync(0xffffffffu, s1, o);
    }
    if (lane == 0) {
        s0 += c2b[0]; s1 += c2b[1];
        float m = fmaxf(s0, s1);
        float e0 = expf(s0 - m), e1 = expf(s1 - m);
        float inv = 1.f / (e0 + e1);
        Aout[row * 2 + 0] = e0 * inv;
        Aout[row * 2 + 1] = e1 * inv;
    }
}

// ---------------- pooling: sub & graph embeddings (block per graph) --------
__global__ void pool_kernel(const float* __restrict__ Hh,
                            const float* __restrict__ Aa,
                            float* __restrict__ sub_out,
                            float* __restrict__ graph_out) {
    __shared__ float sa0[NPG];
    const int g = blockIdx.x, t = threadIdx.x;   // 256 threads
    if (t < NPG) sa0[t] = Aa[(g * NPG + t) * 2];
    __syncthreads();
    float sh = 0.f, ss = 0.f;
    const size_t base = (size_t)g * NPG * HH;
    for (int r = 0; r < NPG; ++r) {
        float hv = Hh[base + r * HH + t];
        sh += hv;
        ss += sa0[r] * hv;
    }
    sub_out[g * HH + t] = ss;
    graph_out[g * HH + t] = sh * (1.f / NPG);
}

// ---------------- pooled adjacency diag penalty (block per graph) ----------
__global__ void adj_kernel(const float* __restrict__ Aa,
                           const int* __restrict__ src,
                           const int* __restrict__ dst) {
    const int g = blockIdx.x, t = threadIdx.x;   // 128 threads
    float m00 = 0.f, m01 = 0.f, m10 = 0.f, m11 = 0.f;
    for (int e = t; e < EPG; e += 128) {
        int se = src[g * EPG + e], de = dst[g * EPG + e];
        float a0 = Aa[se * 2], a1 = Aa[se * 2 + 1];
        float b0 = Aa[de * 2], b1 = Aa[de * 2 + 1];
        m00 += a0 * b0; m01 += a0 * b1;
        m10 += a1 * b0; m11 += a1 * b1;
    }
    __shared__ float red[4][128];
    red[0][t] = m00; red[1][t] = m01; red[2][t] = m10; red[3][t] = m11;
    __syncthreads();
    for (int s = 64; s > 0; s >>= 1) {
        if (t < s) {
            red[0][t] += red[0][t + s]; red[1][t] += red[1][t + s];
            red[2][t] += red[2][t + s]; red[3][t] += red[3][t + s];
        }
        __syncthreads();
    }
    if (t == 0) {
        float r0 = fmaxf(fabsf(red[0][0]) + fabsf(red[1][0]), 1e-12f);
        float r1 = fmaxf(fabsf(red[2][0]) + fabsf(red[3][0]), 1e-12f);
        float e0 = red[0][0] / r0 - 1.f;
        float e1 = red[3][0] / r1 - 1.f;
        d_pen[g] = 0.5f * (e0 * e0 + e1 * e1);
    }
}

__global__ void pen_reduce_kernel(float* __restrict__ outp) {
    __shared__ float s[BB];
    s[threadIdx.x] = d_pen[threadIdx.x];
    __syncthreads();
    for (int st = BB / 2; st > 0; st >>= 1) {
        if (threadIdx.x < st) s[threadIdx.x] += s[threadIdx.x + st];
        __syncthreads();
    }
    if (threadIdx.x == 0) outp[0] = s[0] * (1.f / BB);
}

// ---------------- classifier head (block per graph) ------------------------
__global__ void head_kernel(const float* __restrict__ sub,
                            const float* __restrict__ l1w,
                            const float* __restrict__ l1b,
                            const float* __restrict__ l2w,
                            const float* __restrict__ l2b,
                            float* __restrict__ outp) {
    __shared__ float ssub[HH];
    __shared__ float red0[HH], red1[HH];
    const int r = blockIdx.x, t = threadIdx.x;   // 256 threads
    ssub[t] = sub[r * HH + t];
    __syncthreads();
    float acc = l1b[t];
    #pragma unroll 8
    for (int k = 0; k < HH; ++k) acc += ssub[k] * l1w[k * HH + t];
    float zc = fmaxf(acc, 0.f);
    red0[t] = zc * l2w[t * 2 + 0];
    red1[t] = zc * l2w[t * 2 + 1];
    __syncthreads();
    for (int s = 128; s > 0; s >>= 1) {
        if (t < s) { red0[t] += red0[t + s]; red1[t] += red1[t + s]; }
        __syncthreads();
    }
    if (t == 0) {
        float s0 = red0[0] + l2b[0], s1 = red1[0] + l2b[1];
        float m = fmaxf(s0, s1);
        float lse = m + logf(expf(s0 - m) + expf(s1 - m));
        outp[r * 2 + 0] = s0 - lse;
        outp[r * 2 + 1] = s1 - lse;
    }
}

// ---------------- launch ----------------------------------------------------
extern "C" void kernel_launch(void* const* d_in, const int* in_sizes, int n_in,
                              void* d_out, int out_size) {
    const float* x    = (const float*)d_in[0];
    const int*   ei   = (const int*)d_in[1];
    const int*   src  = ei;
    const int*   dst  = ei + EE;
    const float* w0_1 = (const float*)d_in[3];
    const float* b0_1 = (const float*)d_in[4];
    const float* w0_2 = (const float*)d_in[5];
    const float* b0_2 = (const float*)d_in[6];
    const float* g0   = (const float*)d_in[7];
    const float* be0  = (const float*)d_in[8];
    const float* wl1  = (const float*)d_in[9];
    const float* bl1  = (const float*)d_in[10];
    const float* wl2  = (const float*)d_in[11];
    const float* bl2  = (const float*)d_in[12];
    const float* gl   = (const float*)d_in[13];
    const float* bel  = (const float*)d_in[14];
    const float* c1w  = (const float*)d_in[15];
    const float* c1b  = (const float*)d_in[16];
    const float* c2w  = (const float*)d_in[17];
    const float* c2b  = (const float*)d_in[18];
    const float* l1w  = (const float*)d_in[19];
    const float* l1b  = (const float*)d_in[20];
    const float* l2w  = (const float*)d_in[21];
    const float* l2b  = (const float*)d_in[22];

    float* out        = (float*)d_out;
    float* out_logits = out;                         // [B, 2]
    float* out_sub    = out + BB * 2;                // [B, H]
    float* out_graph  = out + BB * 2 + BB * HH;      // [B, H]
    float* out_pen    = out + BB * 2 + 2 * BB * HH;  // scalar

    float *zb, *tb, *hb, *ab;
    cudaGetSymbolAddress((void**)&zb, d_z);
    cudaGetSymbolAddress((void**)&tb, d_t);
    cudaGetSymbolAddress((void**)&hb, d_h);
    cudaGetSymbolAddress((void**)&ab, d_a);

    cudaFuncSetAttribute(agg_kernel<FIN>, cudaFuncAttributeMaxDynamicSharedMemorySize,
                         NPG * FIN * 4);
    cudaFuncSetAttribute(agg_kernel<HH>, cudaFuncAttributeMaxDynamicSharedMemorySize,
                         NPG * HH * 4);

    const dim3 gemm_grid(HH / 128, NN / 128);

    // ---- GIN layer 0 (F_IN -> H -> H) ----
    agg_kernel<FIN><<<BB, FIN, NPG * FIN * 4>>>(x, src, dst, zb);
    gemm_bf16x3<<<gemm_grid, 256>>>(zb, w0_1, b0_1, tb, FIN, HH, 1);
    gemm_bf16x3<<<gemm_grid, 256>>>(tb, w0_2, b0_2, zb, HH, HH, 1);
    bn_zero_kernel<<<1, 512>>>();
    bn_stats_kernel<<<NN / 256, 256>>>(zb);
    bn_apply_kernel<<<(NN * HH) / 256, 256>>>(zb, g0, be0, hb);

    // ---- GIN layers 1..2 (H -> H -> H) ----
    for (int i = 0; i < 2; ++i) {
        agg_kernel<HH><<<BB, HH, NPG * HH * 4>>>(hb, src, dst, zb);
        gemm_bf16x3<<<gemm_grid, 256>>>(zb, wl1 + i * HH * HH, bl1 + i * HH,
                                        tb, HH, HH, 1);
        gemm_bf16x3<<<gemm_grid, 256>>>(tb, wl2 + i * HH * HH, bl2 + i * HH,
                                        zb, HH, HH, 1);
        bn_zero_kernel<<<1, 512>>>();
        bn_stats_kernel<<<NN / 256, 256>>>(zb);
        bn_apply_kernel<<<(NN * HH) / 256, 256>>>(zb, gl + i * HH, bel + i * HH, hb);
    }

    // ---- assignment: a = softmax(tanh(h@c1w+c1b) @ c2w + c2b) ----
    gemm_bf16x3<<<gemm_grid, 256>>>(hb, c1w, c1b, tb, HH, HH, 2);
    assign_kernel<<<NN / 8, 256>>>(tb, c2w, c2b, ab);

    // ---- pooling / penalty / head ----
    pool_kernel<<<BB, 256>>>(hb, ab, out_sub, out_graph);
    adj_kernel<<<BB, 128>>>(ab, src, dst);
    pen_reduce_kernel<<<1, BB>>>(out_pen);
    head_kernel<<<BB, 256>>>(out_sub, l1w, l1b, l2w, l2b, out_logits);
}